// round 16
// baseline (speedup 1.0000x reference)
#include <cuda_runtime.h>
#include <cuda_bf16.h>
#include <math.h>

// ---------------- problem constants ----------------
#define BATCH    2
#define SEQ      2048
#define DMODEL   2048
#define NHEADS   16
#define NKV      4
#define HDIM     128
#define KVDIM    (NKV * HDIM)          // 512
#define NTOK     (BATCH * SEQ)         // 4096
#define CLIPV    8.0f
#define LN_EPS   1e-5f
#define THETA    500000.0f
#define SCALE    0.08838834764831845f  // 1/sqrt(128)
#define SMAX_OFF 12.0f                 // fixed softmax offset (scores can't overflow)
#define NQT      (SEQ / 64)            // 32 q-tiles

// ---------------- scratch (no allocs allowed) ----------------
__device__ float g_q  [(size_t)NTOK * DMODEL];   // tf32-rounded, pre-scaled
__device__ float g_k  [(size_t)NTOK * KVDIM];    // tf32-rounded
__device__ float g_v  [(size_t)NTOK * KVDIM];    // tf32-rounded
__device__ float g_att[(size_t)NTOK * DMODEL];   // tf32-rounded at store
__device__ float g_xr [(size_t)NTOK * DMODEL];   // tf32(x)
__device__ float g_wqr[(size_t)DMODEL * DMODEL]; // tf32(wq)
__device__ float g_wkr[(size_t)KVDIM * DMODEL];  // tf32(wk)
__device__ float g_wvr[(size_t)KVDIM * DMODEL];  // tf32(wv)
__device__ float g_wor[(size_t)DMODEL * DMODEL]; // tf32(wo)
__device__ float g_cos[SEQ * (HDIM / 2)];
__device__ float g_sin[SEQ * (HDIM / 2)];

// ---------------- helpers ----------------
__device__ __forceinline__ unsigned f2tf(float f) {
    unsigned u;
    asm("cvt.rna.tf32.f32 %0, %1;" : "=r"(u) : "f"(f));
    return u;
}

__device__ __forceinline__ void mma_tf32(float* d, unsigned a0, unsigned a1,
                                         unsigned a2, unsigned a3,
                                         unsigned b0, unsigned b1) {
    asm volatile(
        "mma.sync.aligned.m16n8k8.row.col.f32.tf32.tf32.f32 "
        "{%0,%1,%2,%3}, {%4,%5,%6,%7}, {%8,%9}, {%0,%1,%2,%3};"
        : "+f"(d[0]), "+f"(d[1]), "+f"(d[2]), "+f"(d[3])
        : "r"(a0), "r"(a1), "r"(a2), "r"(a3), "r"(b0), "r"(b1));
}

#define LDSM_X4(r0, r1, r2, r3, addr) \
    asm volatile("ldmatrix.sync.aligned.m8n8.x4.shared.b16 {%0,%1,%2,%3}, [%4];" \
                 : "=r"(r0), "=r"(r1), "=r"(r2), "=r"(r3) : "r"(addr))
#define LDSM_X2(r0, r1, addr) \
    asm volatile("ldmatrix.sync.aligned.m8n8.x2.shared.b16 {%0,%1}, [%2];" \
                 : "=r"(r0), "=r"(r1) : "r"(addr))

#define CP_ASYNC16(dst, src) \
    asm volatile("cp.async.cg.shared.global [%0], [%1], 16;" :: "r"(dst), "l"(src))
#define CP_COMMIT() asm volatile("cp.async.commit_group;" ::: "memory")
#define CP_WAIT1()  asm volatile("cp.async.wait_group 1;" ::: "memory")

// ---------------- RoPE tables ----------------
__global__ void rope_table_kernel() {
    int idx = blockIdx.x * 256 + threadIdx.x;
    if (idx >= SEQ * 64) return;
    int t = idx >> 6;
    int i = idx & 63;
    float inv = powf(THETA, -(2.0f * (float)i) / 128.0f);
    float a = (float)t * inv;
    g_cos[idx] = cosf(a);
    g_sin[idx] = sinf(a);
}

// ---------------- fused tf32 pre-round prepass (single launch) ----------------
__global__ __launch_bounds__(256)
void tf32_round_all_kernel(const float4* __restrict__ x,  float4* __restrict__ xr,
                           const float4* __restrict__ wq, float4* __restrict__ wqr,
                           const float4* __restrict__ wk, float4* __restrict__ wkr,
                           const float4* __restrict__ wv, float4* __restrict__ wvr,
                           const float4* __restrict__ wo, float4* __restrict__ wor) {
    const float4* in;
    float4* out;
    int n4;
    switch (blockIdx.y) {
        case 0: in = x;  out = xr;  n4 = NTOK * DMODEL / 4;   break;
        case 1: in = wq; out = wqr; n4 = DMODEL * DMODEL / 4; break;
        case 2: in = wk; out = wkr; n4 = KVDIM * DMODEL / 4;  break;
        case 3: in = wv; out = wvr; n4 = KVDIM * DMODEL / 4;  break;
        default: in = wo; out = wor; n4 = DMODEL * DMODEL / 4; break;
    }
    int i = blockIdx.x * 256 + threadIdx.x;
    if (i >= n4) return;
    float4 v = in[i];
    float4 o;
    o.x = __uint_as_float(f2tf(v.x));
    o.y = __uint_as_float(f2tf(v.y));
    o.z = __uint_as_float(f2tf(v.z));
    o.w = __uint_as_float(f2tf(v.w));
    out[i] = o;
}

// ---------------- tf32 GEMM (R12-proven: 8 warps, 64x32, ldmatrix, BK=16) ----
#define SM_STRIDE 20   // floats per row (16 data + 4 pad)

template <bool DO_CLIP, bool TF32OUT>
__device__ __forceinline__
void gemm_body(const float* __restrict__ A, const float* __restrict__ W,
               const float* __restrict__ bias, float* __restrict__ C,
               int N, int K, int bm, int bn) {
    __shared__ float sA[2][128 * SM_STRIDE];
    __shared__ float sB[2][128 * SM_STRIDE];

    const int tid = threadIdx.x;
    const int wid = tid >> 5;
    const int lane = tid & 31;

    const int warp_m = wid & 1;
    const int warp_n = wid >> 1;
    const int mbase = warp_m * 64;
    const int nbase = warp_n * 32;
    const int r = lane >> 2;
    const int c = lane & 3;

    const int c0row = (tid * 2) >> 2,       c0col = (tid * 2) & 3;
    const int c1row = (tid * 2 + 1) >> 2,   c1col = (tid * 2 + 1) & 3;

    unsigned sA_base = (unsigned)__cvta_generic_to_shared(&sA[0][0]);
    unsigned sB_base = (unsigned)__cvta_generic_to_shared(&sB[0][0]);

    const unsigned aoff = ((mbase + (lane & 15)) * SM_STRIDE + ((lane & 16) >> 2)) * 4;
    const unsigned boff = ((nbase + (lane & 7)) * SM_STRIDE + ((lane & 8) >> 1)) * 4;

    float acc[4][4][4];
#pragma unroll
    for (int mt = 0; mt < 4; mt++)
#pragma unroll
        for (int nt = 0; nt < 4; nt++)
#pragma unroll
            for (int i = 0; i < 4; i++) acc[mt][nt][i] = 0.f;

    const int nk = K / 16;

    auto load_tile = [&](int buf, int k0) {
        unsigned sa = sA_base + buf * (128 * SM_STRIDE * 4);
        unsigned sb = sB_base + buf * (128 * SM_STRIDE * 4);
        CP_ASYNC16(sa + (c0row * SM_STRIDE + c0col * 4) * 4,
                   A + (size_t)(bm + c0row) * K + k0 + c0col * 4);
        CP_ASYNC16(sa + (c1row * SM_STRIDE + c1col * 4) * 4,
                   A + (size_t)(bm + c1row) * K + k0 + c1col * 4);
        CP_ASYNC16(sb + (c0row * SM_STRIDE + c0col * 4) * 4,
                   W + (size_t)(bn + c0row) * K + k0 + c0col * 4);
        CP_ASYNC16(sb + (c1row * SM_STRIDE + c1col * 4) * 4,
                   W + (size_t)(bn + c1row) * K + k0 + c1col * 4);
    };

    load_tile(0, 0);  CP_COMMIT();
    load_tile(1, 16); CP_COMMIT();
    CP_WAIT1();
    __syncthreads();

    for (int kt = 0; kt < nk; kt++) {
        int cur = kt & 1;
        unsigned abase = sA_base + cur * (128 * SM_STRIDE * 4) + aoff;
        unsigned bbase = sB_base + cur * (128 * SM_STRIDE * 4) + boff;

#pragma unroll
        for (int s = 0; s < 2; s++) {
            unsigned a[4][4], b[4][2];
#pragma unroll
            for (int mt = 0; mt < 4; mt++) {
                unsigned addr = abase + (mt * 16 * SM_STRIDE + s * 8) * 4;
                LDSM_X4(a[mt][0], a[mt][1], a[mt][2], a[mt][3], addr);
            }
#pragma unroll
            for (int nt = 0; nt < 4; nt++) {
                unsigned addr = bbase + (nt * 8 * SM_STRIDE + s * 8) * 4;
                LDSM_X2(b[nt][0], b[nt][1], addr);
            }
#pragma unroll
            for (int mt = 0; mt < 4; mt++)
#pragma unroll
                for (int nt = 0; nt < 4; nt++)
                    mma_tf32(acc[mt][nt], a[mt][0], a[mt][1], a[mt][2], a[mt][3],
                             b[nt][0], b[nt][1]);
        }

        __syncthreads();
        if (kt + 2 < nk) load_tile(cur, (kt + 2) * 16);
        CP_COMMIT();
        CP_WAIT1();
        __syncthreads();
    }

#pragma unroll
    for (int mt = 0; mt < 4; mt++) {
#pragma unroll
        for (int nt = 0; nt < 4; nt++) {
            int row = bm + mbase + mt * 16 + r;
            int col = bn + nbase + nt * 8 + 2 * c;
            float b0 = bias[col], b1 = bias[col + 1];
            float v0 = acc[mt][nt][0] + b0;
            float v1 = acc[mt][nt][1] + b1;
            float v2 = acc[mt][nt][2] + b0;
            float v3 = acc[mt][nt][3] + b1;
            if (DO_CLIP) {
                v0 = fminf(fmaxf(v0, -CLIPV), CLIPV);
                v1 = fminf(fmaxf(v1, -CLIPV), CLIPV);
                v2 = fminf(fmaxf(v2, -CLIPV), CLIPV);
                v3 = fminf(fmaxf(v3, -CLIPV), CLIPV);
            }
            if (TF32OUT) {
                v0 = __uint_as_float(f2tf(v0));
                v1 = __uint_as_float(f2tf(v1));
                v2 = __uint_as_float(f2tf(v2));
                v3 = __uint_as_float(f2tf(v3));
            }
            *(float2*)(C + (size_t)row * N + col)       = make_float2(v0, v1);
            *(float2*)(C + (size_t)(row + 8) * N + col) = make_float2(v2, v3);
        }
    }
}

// fused QKV projection: grid (24, 32). cb 0-15 -> Q, 16-19 -> K, 20-23 -> V
__global__ __launch_bounds__(256, 2)
void gemm_qkv_kernel(const float* __restrict__ x,
                     const float* __restrict__ wq, const float* __restrict__ bq,
                     const float* __restrict__ wk, const float* __restrict__ bk,
                     const float* __restrict__ wv, const float* __restrict__ bv,
                     float* __restrict__ qout, float* __restrict__ kout,
                     float* __restrict__ vout) {
    int cb = blockIdx.x;
    int bm = blockIdx.y * 128;
    if (cb < 16) {
        gemm_body<true, false>(x, wq, bq, qout, DMODEL, DMODEL, bm, cb * 128);
    } else if (cb < 20) {
        gemm_body<true, false>(x, wk, bk, kout, KVDIM, DMODEL, bm, (cb - 16) * 128);
    } else {
        gemm_body<true, true>(x, wv, bv, vout, KVDIM, DMODEL, bm, (cb - 20) * 128);
    }
}

// output projection
__global__ __launch_bounds__(256, 2)
void gemm_o_kernel(const float* __restrict__ A, const float* __restrict__ wo,
                   const float* __restrict__ bo, float* __restrict__ C) {
    gemm_body<false, false>(A, wo, bo, C, DMODEL, DMODEL, blockIdx.y * 128, blockIdx.x * 128);
}

// ---------------- LayerNorm + RoPE body ----------------
template <int WIDTH, bool DO_SCALE>
__device__ __forceinline__
void ln_body(float* __restrict__ x, const float* __restrict__ gamma,
             const float* __restrict__ beta) {
    constexpr int NT  = 256;
    constexpr int PER = WIDTH / NT;
    __shared__ float sh[WIDTH];
    __shared__ float wred[16];
    __shared__ float s_mu, s_rstd;

    int row = blockIdx.x;
    int t = row & (SEQ - 1);
    float* xr = x + (size_t)row * WIDTH;

    float v[PER];
    float sum = 0.f, sq = 0.f;
#pragma unroll
    for (int i = 0; i < PER; i++) {
        v[i] = xr[threadIdx.x + i * NT];
        sum += v[i];
        sq  += v[i] * v[i];
    }
#pragma unroll
    for (int o = 16; o; o >>= 1) {
        sum += __shfl_xor_sync(0xffffffffu, sum, o);
        sq  += __shfl_xor_sync(0xffffffffu, sq, o);
    }
    int wid = threadIdx.x >> 5, lane = threadIdx.x & 31;
    if (lane == 0) { wred[wid] = sum; wred[8 + wid] = sq; }
    __syncthreads();
    if (threadIdx.x == 0) {
        float s = 0.f, s2 = 0.f;
#pragma unroll
        for (int i = 0; i < 8; i++) { s += wred[i]; s2 += wred[8 + i]; }
        float mu  = s / (float)WIDTH;
        float var = s2 / (float)WIDTH - mu * mu;
        s_mu = mu;
        s_rstd = rsqrtf(var + LN_EPS);
    }
    __syncthreads();
    float mu = s_mu, rstd = s_rstd;
#pragma unroll
    for (int i = 0; i < PER; i++) {
        int e = threadIdx.x + i * NT;
        sh[e] = (v[i] - mu) * rstd * gamma[e] + beta[e];
    }
    __syncthreads();
#pragma unroll
    for (int i = 0; i < PER; i++) {
        int e = threadIdx.x + i * NT;
        int d = e & 127;
        int i64 = d & 63;
        float cc = g_cos[t * 64 + i64];
        float ss = g_sin[t * 64 + i64];
        float val = sh[e];
        float other = (d < 64) ? -sh[e + 64] : sh[e - 64];
        float res = val * cc + other * ss;
        if (DO_SCALE) res *= SCALE;
        xr[e] = __uint_as_float(f2tf(res));
    }
}

// merged LN launch: blockIdx.y = 0 -> Q row (width 2048, scaled),
//                   blockIdx.y = 1 -> K row (width 512)
__global__ __launch_bounds__(256)
void ln_rope_both_kernel(float* __restrict__ qx, const float* __restrict__ qg,
                         const float* __restrict__ qbeta,
                         float* __restrict__ kx, const float* __restrict__ kg,
                         const float* __restrict__ kbeta) {
    if (blockIdx.y == 0) {
        ln_body<DMODEL, true>(qx, qg, qbeta);
    } else {
        ln_body<KVDIM, false>(kx, kg, kbeta);
    }
}

// ---------------- MMA flash attention (R12-proven, unchanged) ----------------
#define ATTN_SMEM_F (64*132 + 2*32*132 + 2*32*132 + 4*16*36)

__global__ __launch_bounds__(128, 2)
void attn_mma_kernel(const float* __restrict__ q, const float* __restrict__ k,
                     const float* __restrict__ v, float* __restrict__ o) {
    extern __shared__ float sm[];
    float* Qs = sm;
    float* Ks = Qs + 64 * 132;
    float* Vs = Ks + 2 * 32 * 132;
    float* Ps = Vs + 2 * 32 * 132;

    const int tid = threadIdx.x;
    const int w = tid >> 5, lane = tid & 31;
    const int r = lane >> 2, c = lane & 3;
    const int bh = blockIdx.y;
    const int b = bh >> 4, h = bh & 15, kvh = h >> 2;

    const float* kbase = k + ((size_t)b * SEQ) * KVDIM + kvh * HDIM;
    const float* vbase = v + ((size_t)b * SEQ) * KVDIM + kvh * HDIM;
    float* Pw = Ps + w * 16 * 36;

    unsigned Ks_base = (unsigned)__cvta_generic_to_shared(Ks);
    const unsigned koff = ((lane & 7) * 132 + ((lane & 8) >> 1)) * 4;

#pragma unroll 1
    for (int pass = 0; pass < 2; pass++) {
        const int qt = pass ? (NQT - 1 - (int)blockIdx.x) : (int)blockIdx.x;
        const int q0 = qt * 64;
        const float* qbase = q + ((size_t)(b * SEQ + q0)) * DMODEL + h * HDIM;

        __syncthreads();

#pragma unroll
        for (int i = 0; i < 16; i++) {
            int idx = tid + i * 128;
            int qr = idx >> 5, d4 = idx & 31;
            *(float4*)&Qs[qr * 132 + d4 * 4] =
                *(const float4*)(qbase + (size_t)qr * DMODEL + d4 * 4);
        }
        __syncthreads();

        unsigned qa[16][4];
#pragma unroll
        for (int kb = 0; kb < 16; kb++) {
            qa[kb][0] = __float_as_uint(Qs[(w * 16 + r) * 132 + kb * 8 + c]);
            qa[kb][1] = __float_as_uint(Qs[(w * 16 + r + 8) * 132 + kb * 8 + c]);
            qa[kb][2] = __float_as_uint(Qs[(w * 16 + r) * 132 + kb * 8 + c + 4]);
            qa[kb][3] = __float_as_uint(Qs[(w * 16 + r + 8) * 132 + kb * 8 + c + 4]);
        }

        auto loadkv = [&](int kt) {
            int buf = kt & 1;
            float* Kd = Ks + buf * 32 * 132;
            float* Vd = Vs + buf * 32 * 132;
            const float* ksrc = kbase + (size_t)(kt * 32) * KVDIM;
            const float* vsrc = vbase + (size_t)(kt * 32) * KVDIM;
#pragma unroll
            for (int i = 0; i < 8; i++) {
                int j = tid + i * 128;
                int row = j >> 5, cc = j & 31;
                unsigned kd = (unsigned)__cvta_generic_to_shared(Kd + row * 132 + cc * 4);
                CP_ASYNC16(kd, ksrc + (size_t)row * KVDIM + cc * 4);
                unsigned vd = (unsigned)__cvta_generic_to_shared(Vd + row * 132 + cc * 4);
                CP_ASYNC16(vd, vsrc + (size_t)row * KVDIM + cc * 4);
            }
        };

        float oacc[16][4];
#pragma unroll
        for (int nb = 0; nb < 16; nb++)
#pragma unroll
            for (int i = 0; i < 4; i++) oacc[nb][i] = 0.f;
        float l0 = 0.f, l1 = 0.f;

        const int row0 = q0 + w * 16 + r;
        const int row1 = row0 + 8;
        const int ntiles = (q0 + 64) >> 5;

        loadkv(0); CP_COMMIT();

        for (int kt = 0; kt < ntiles; kt++) {
            __syncthreads();
            if (kt + 1 < ntiles) loadkv(kt + 1);
            CP_COMMIT();
            CP_WAIT1();
            __syncthreads();

            unsigned kbuf = Ks_base + (kt & 1) * (32 * 132 * 4) + koff;
            const float* Vb = Vs + (kt & 1) * 32 * 132;

            float sacc[4][4];
#pragma unroll
            for (int nb = 0; nb < 4; nb++)
#pragma unroll
                for (int i = 0; i < 4; i++) sacc[nb][i] = 0.f;

#pragma unroll
            for (int kb = 0; kb < 16; kb++) {
#pragma unroll
                for (int nb = 0; nb < 4; nb++) {
                    unsigned b0, b1;
                    LDSM_X2(b0, b1, kbuf + (nb * 8 * 132 + kb * 8) * 4);
                    mma_tf32(sacc[nb], qa[kb][0], qa[kb][1], qa[kb][2], qa[kb][3],
                             b0, b1);
                }
            }

            bool mask_tile = (kt * 32 + 31 > q0 + w * 16);
            __syncwarp();
#pragma unroll
            for (int nb = 0; nb < 4; nb++) {
                int col = kt * 32 + nb * 8 + 2 * c;
                float p0 = __expf(sacc[nb][0] - SMAX_OFF);
                float p1 = __expf(sacc[nb][1] - SMAX_OFF);
                float p2 = __expf(sacc[nb][2] - SMAX_OFF);
                float p3 = __expf(sacc[nb][3] - SMAX_OFF);
                if (mask_tile) {
                    if (col     > row0) p0 = 0.f;
                    if (col + 1 > row0) p1 = 0.f;
                    if (col     > row1) p2 = 0.f;
                    if (col + 1 > row1) p3 = 0.f;
                }
                l0 += p0 + p1;
                l1 += p2 + p3;
                *(float2*)&Pw[r * 36 + nb * 8 + 2 * c] =
                    make_float2(__uint_as_float(f2tf(p0)), __uint_as_float(f2tf(p1)));
                *(float2*)&Pw[(r + 8) * 36 + nb * 8 + 2 * c] =
                    make_float2(__uint_as_float(f2tf(p2)), __uint_as_float(f2tf(p3)));
            }
            __syncwarp();

#pragma unroll
            for (int kb = 0; kb < 4; kb++) {
                unsigned a0 = __float_as_uint(Pw[r * 36 + kb * 8 + c]);
                unsigned a1 = __float_as_uint(Pw[(r + 8) * 36 + kb * 8 + c]);
                unsigned a2 = __float_as_uint(Pw[r * 36 + kb * 8 + c + 4]);
                unsigned a3 = __float_as_uint(Pw[(r + 8) * 36 + kb * 8 + c + 4]);
#pragma unroll
                for (int nb = 0; nb < 16; nb++) {
                    unsigned b0 = __float_as_uint(Vb[(kb * 8 + c) * 132 + nb * 8 + r]);
                    unsigned b1 = __float_as_uint(Vb[(kb * 8 + c + 4) * 132 + nb * 8 + r]);
                    mma_tf32(oacc[nb], a0, a1, a2, a3, b0, b1);
                }
            }
        }

        l0 += __shfl_xor_sync(0xffffffffu, l0, 1);
        l0 += __shfl_xor_sync(0xffffffffu, l0, 2);
        l1 += __shfl_xor_sync(0xffffffffu, l1, 1);
        l1 += __shfl_xor_sync(0xffffffffu, l1, 2);
        float inv0 = 1.f / l0, inv1 = 1.f / l1;

        float* ob0 = o + ((size_t)(b * SEQ + row0)) * DMODEL + h * HDIM;
        float* ob1 = ob0 + (size_t)8 * DMODEL;
#pragma unroll
        for (int nb = 0; nb < 16; nb++) {
            *(float2*)(ob0 + nb * 8 + 2 * c) = make_float2(
                __uint_as_float(f2tf(oacc[nb][0] * inv0)),
                __uint_as_float(f2tf(oacc[nb][1] * inv0)));
            *(float2*)(ob1 + nb * 8 + 2 * c) = make_float2(
                __uint_as_float(f2tf(oacc[nb][2] * inv1)),
                __uint_as_float(f2tf(oacc[nb][3] * inv1)));
        }
    }
}

// ---------------- host launch ----------------
extern "C" void kernel_launch(void* const* d_in, const int* in_sizes, int n_in,
                              void* d_out, int out_size) {
    const float* x       = (const float*)d_in[0];
    const float* wq      = (const float*)d_in[1];
    const float* bq      = (const float*)d_in[2];
    const float* wk      = (const float*)d_in[3];
    const float* bk      = (const float*)d_in[4];
    const float* wv      = (const float*)d_in[5];
    const float* bv      = (const float*)d_in[6];
    const float* wo      = (const float*)d_in[7];
    const float* bo      = (const float*)d_in[8];
    const float* q_gamma = (const float*)d_in[9];
    const float* q_beta  = (const float*)d_in[10];
    const float* k_gamma = (const float*)d_in[11];
    const float* k_beta  = (const float*)d_in[12];
    float* out = (float*)d_out;

    float *qb, *kb, *vb, *ab, *xr, *wqr, *wkr, *wvr, *wor;
    cudaGetSymbolAddress((void**)&qb,  g_q);
    cudaGetSymbolAddress((void**)&kb,  g_k);
    cudaGetSymbolAddress((void**)&vb,  g_v);
    cudaGetSymbolAddress((void**)&ab,  g_att);
    cudaGetSymbolAddress((void**)&xr,  g_xr);
    cudaGetSymbolAddress((void**)&wqr, g_wqr);
    cudaGetSymbolAddress((void**)&wkr, g_wkr);
    cudaGetSymbolAddress((void**)&wvr, g_wvr);
    cudaGetSymbolAddress((void**)&wor, g_wor);

    const int attn_smem = ATTN_SMEM_F * sizeof(float);
    cudaFuncSetAttribute(attn_mma_kernel,
                         cudaFuncAttributeMaxDynamicSharedMemorySize, attn_smem);

    rope_table_kernel<<<(SEQ * 64 + 255) / 256, 256>>>();

    const int NX = NTOK * DMODEL / 4;
    tf32_round_all_kernel<<<dim3((NX + 255) / 256, 5), 256>>>(
        (const float4*)x,  (float4*)xr,
        (const float4*)wq, (float4*)wqr,
        (const float4*)wk, (float4*)wkr,
        (const float4*)wv, (float4*)wvr,
        (const float4*)wo, (float4*)wor);

    gemm_qkv_kernel<<<dim3(24, NTOK / 128), 256>>>(
        xr, wqr, bq, wkr, bk, wvr, bv, qb, kb, vb);

    ln_rope_both_kernel<<<dim3(NTOK, 2), 256>>>(qb, q_gamma, q_beta,
                                                kb, k_gamma, k_beta);

    attn_mma_kernel<<<dim3(NQT / 2, BATCH * NHEADS), 128, attn_smem>>>(qb, kb, vb, ab);

    gemm_o_kernel<<<dim3(DMODEL / 128, NTOK / 128), 256>>>(ab, wor, bo, out);
}

// round 17
// speedup vs baseline: 1.7603x; 1.7603x over previous
#include <cuda_runtime.h>
#include <cuda_bf16.h>
#include <math.h>

// ---------------- problem constants ----------------
#define BATCH    2
#define SEQ      2048
#define DMODEL   2048
#define NHEADS   16
#define NKV      4
#define HDIM     128
#define KVDIM    (NKV * HDIM)          // 512
#define NTOK     (BATCH * SEQ)         // 4096
#define CLIPV    8.0f
#define LN_EPS   1e-5f
#define THETA    500000.0f
#define SCALE    0.08838834764831845f  // 1/sqrt(128)
#define SMAX_OFF 12.0f                 // fixed softmax offset (scores can't overflow)
#define NQT      (SEQ / 64)            // 32 q-tiles

// ---------------- scratch (no allocs allowed) ----------------
__device__ float g_q  [(size_t)NTOK * DMODEL];   // tf32-rounded, pre-scaled
__device__ float g_k  [(size_t)NTOK * KVDIM];    // tf32-rounded
__device__ float g_v  [(size_t)NTOK * KVDIM];    // tf32-rounded
__device__ float g_att[(size_t)NTOK * DMODEL];   // tf32-rounded at store
__device__ float g_xr [(size_t)NTOK * DMODEL];   // tf32(x)
__device__ float g_wqr[(size_t)DMODEL * DMODEL]; // tf32(wq)
__device__ float g_wkr[(size_t)KVDIM * DMODEL];  // tf32(wk)
__device__ float g_wvr[(size_t)KVDIM * DMODEL];  // tf32(wv)
__device__ float g_wor[(size_t)DMODEL * DMODEL]; // tf32(wo)
__device__ float g_cos[SEQ * (HDIM / 2)];
__device__ float g_sin[SEQ * (HDIM / 2)];

// ---------------- helpers ----------------
__device__ __forceinline__ unsigned f2tf(float f) {
    unsigned u;
    asm("cvt.rna.tf32.f32 %0, %1;" : "=r"(u) : "f"(f));
    return u;
}

__device__ __forceinline__ void mma_tf32(float* d, unsigned a0, unsigned a1,
                                         unsigned a2, unsigned a3,
                                         unsigned b0, unsigned b1) {
    asm volatile(
        "mma.sync.aligned.m16n8k8.row.col.f32.tf32.tf32.f32 "
        "{%0,%1,%2,%3}, {%4,%5,%6,%7}, {%8,%9}, {%0,%1,%2,%3};"
        : "+f"(d[0]), "+f"(d[1]), "+f"(d[2]), "+f"(d[3])
        : "r"(a0), "r"(a1), "r"(a2), "r"(a3), "r"(b0), "r"(b1));
}

#define LDSM_X4(r0, r1, r2, r3, addr) \
    asm volatile("ldmatrix.sync.aligned.m8n8.x4.shared.b16 {%0,%1,%2,%3}, [%4];" \
                 : "=r"(r0), "=r"(r1), "=r"(r2), "=r"(r3) : "r"(addr))
#define LDSM_X2(r0, r1, addr) \
    asm volatile("ldmatrix.sync.aligned.m8n8.x2.shared.b16 {%0,%1}, [%2];" \
                 : "=r"(r0), "=r"(r1) : "r"(addr))

#define CP_ASYNC16(dst, src) \
    asm volatile("cp.async.cg.shared.global [%0], [%1], 16;" :: "r"(dst), "l"(src))
#define CP_COMMIT() asm volatile("cp.async.commit_group;" ::: "memory")
#define CP_WAIT1()  asm volatile("cp.async.wait_group 1;" ::: "memory")

// ---------------- RoPE tables ----------------
__global__ void rope_table_kernel() {
    int idx = blockIdx.x * 256 + threadIdx.x;
    if (idx >= SEQ * 64) return;
    int t = idx >> 6;
    int i = idx & 63;
    float inv = powf(THETA, -(2.0f * (float)i) / 128.0f);
    float a = (float)t * inv;
    g_cos[idx] = cosf(a);
    g_sin[idx] = sinf(a);
}

// ---------------- fused tf32 pre-round prepass (single launch) ----------------
__global__ __launch_bounds__(256)
void tf32_round_all_kernel(const float4* __restrict__ x,  float4* __restrict__ xr,
                           const float4* __restrict__ wq, float4* __restrict__ wqr,
                           const float4* __restrict__ wk, float4* __restrict__ wkr,
                           const float4* __restrict__ wv, float4* __restrict__ wvr,
                           const float4* __restrict__ wo, float4* __restrict__ wor) {
    const float4* in;
    float4* out;
    int n4;
    switch (blockIdx.y) {
        case 0: in = x;  out = xr;  n4 = NTOK * DMODEL / 4;   break;
        case 1: in = wq; out = wqr; n4 = DMODEL * DMODEL / 4; break;
        case 2: in = wk; out = wkr; n4 = KVDIM * DMODEL / 4;  break;
        case 3: in = wv; out = wvr; n4 = KVDIM * DMODEL / 4;  break;
        default: in = wo; out = wor; n4 = DMODEL * DMODEL / 4; break;
    }
    int i = blockIdx.x * 256 + threadIdx.x;
    if (i >= n4) return;
    float4 v = in[i];
    float4 o;
    o.x = __uint_as_float(f2tf(v.x));
    o.y = __uint_as_float(f2tf(v.y));
    o.z = __uint_as_float(f2tf(v.z));
    o.w = __uint_as_float(f2tf(v.w));
    out[i] = o;
}

// ---------------- tf32 GEMM (proven: 8 warps, 64x32, ldmatrix, BK=16) ----
#define SM_STRIDE 20   // floats per row (16 data + 4 pad)

template <bool DO_CLIP, bool TF32OUT>
__device__ __forceinline__
void gemm_body(const float* __restrict__ A, const float* __restrict__ W,
               const float* __restrict__ bias, float* __restrict__ C,
               int N, int K, int bm, int bn) {
    __shared__ float sA[2][128 * SM_STRIDE];
    __shared__ float sB[2][128 * SM_STRIDE];

    const int tid = threadIdx.x;
    const int wid = tid >> 5;
    const int lane = tid & 31;

    const int warp_m = wid & 1;
    const int warp_n = wid >> 1;
    const int mbase = warp_m * 64;
    const int nbase = warp_n * 32;
    const int r = lane >> 2;
    const int c = lane & 3;

    const int c0row = (tid * 2) >> 2,       c0col = (tid * 2) & 3;
    const int c1row = (tid * 2 + 1) >> 2,   c1col = (tid * 2 + 1) & 3;

    unsigned sA_base = (unsigned)__cvta_generic_to_shared(&sA[0][0]);
    unsigned sB_base = (unsigned)__cvta_generic_to_shared(&sB[0][0]);

    const unsigned aoff = ((mbase + (lane & 15)) * SM_STRIDE + ((lane & 16) >> 2)) * 4;
    const unsigned boff = ((nbase + (lane & 7)) * SM_STRIDE + ((lane & 8) >> 1)) * 4;

    float acc[4][4][4];
#pragma unroll
    for (int mt = 0; mt < 4; mt++)
#pragma unroll
        for (int nt = 0; nt < 4; nt++)
#pragma unroll
            for (int i = 0; i < 4; i++) acc[mt][nt][i] = 0.f;

    const int nk = K / 16;

    auto load_tile = [&](int buf, int k0) {
        unsigned sa = sA_base + buf * (128 * SM_STRIDE * 4);
        unsigned sb = sB_base + buf * (128 * SM_STRIDE * 4);
        CP_ASYNC16(sa + (c0row * SM_STRIDE + c0col * 4) * 4,
                   A + (size_t)(bm + c0row) * K + k0 + c0col * 4);
        CP_ASYNC16(sa + (c1row * SM_STRIDE + c1col * 4) * 4,
                   A + (size_t)(bm + c1row) * K + k0 + c1col * 4);
        CP_ASYNC16(sb + (c0row * SM_STRIDE + c0col * 4) * 4,
                   W + (size_t)(bn + c0row) * K + k0 + c0col * 4);
        CP_ASYNC16(sb + (c1row * SM_STRIDE + c1col * 4) * 4,
                   W + (size_t)(bn + c1row) * K + k0 + c1col * 4);
    };

    load_tile(0, 0);  CP_COMMIT();
    load_tile(1, 16); CP_COMMIT();
    CP_WAIT1();
    __syncthreads();

    for (int kt = 0; kt < nk; kt++) {
        int cur = kt & 1;
        unsigned abase = sA_base + cur * (128 * SM_STRIDE * 4) + aoff;
        unsigned bbase = sB_base + cur * (128 * SM_STRIDE * 4) + boff;

#pragma unroll
        for (int s = 0; s < 2; s++) {
            unsigned a[4][4], b[4][2];
#pragma unroll
            for (int mt = 0; mt < 4; mt++) {
                unsigned addr = abase + (mt * 16 * SM_STRIDE + s * 8) * 4;
                LDSM_X4(a[mt][0], a[mt][1], a[mt][2], a[mt][3], addr);
            }
#pragma unroll
            for (int nt = 0; nt < 4; nt++) {
                unsigned addr = bbase + (nt * 8 * SM_STRIDE + s * 8) * 4;
                LDSM_X2(b[nt][0], b[nt][1], addr);
            }
#pragma unroll
            for (int mt = 0; mt < 4; mt++)
#pragma unroll
                for (int nt = 0; nt < 4; nt++)
                    mma_tf32(acc[mt][nt], a[mt][0], a[mt][1], a[mt][2], a[mt][3],
                             b[nt][0], b[nt][1]);
        }

        __syncthreads();
        if (kt + 2 < nk) load_tile(cur, (kt + 2) * 16);
        CP_COMMIT();
        CP_WAIT1();
        __syncthreads();
    }

#pragma unroll
    for (int mt = 0; mt < 4; mt++) {
#pragma unroll
        for (int nt = 0; nt < 4; nt++) {
            int row = bm + mbase + mt * 16 + r;
            int col = bn + nbase + nt * 8 + 2 * c;
            float b0 = bias[col], b1 = bias[col + 1];
            float v0 = acc[mt][nt][0] + b0;
            float v1 = acc[mt][nt][1] + b1;
            float v2 = acc[mt][nt][2] + b0;
            float v3 = acc[mt][nt][3] + b1;
            if (DO_CLIP) {
                v0 = fminf(fmaxf(v0, -CLIPV), CLIPV);
                v1 = fminf(fmaxf(v1, -CLIPV), CLIPV);
                v2 = fminf(fmaxf(v2, -CLIPV), CLIPV);
                v3 = fminf(fmaxf(v3, -CLIPV), CLIPV);
            }
            if (TF32OUT) {
                v0 = __uint_as_float(f2tf(v0));
                v1 = __uint_as_float(f2tf(v1));
                v2 = __uint_as_float(f2tf(v2));
                v3 = __uint_as_float(f2tf(v3));
            }
            *(float2*)(C + (size_t)row * N + col)       = make_float2(v0, v1);
            *(float2*)(C + (size_t)(row + 8) * N + col) = make_float2(v2, v3);
        }
    }
}

// fused QKV projection: grid (24, 32). cb 0-15 -> Q, 16-19 -> K, 20-23 -> V
__global__ __launch_bounds__(256, 2)
void gemm_qkv_kernel(const float* __restrict__ x,
                     const float* __restrict__ wq, const float* __restrict__ bq,
                     const float* __restrict__ wk, const float* __restrict__ bk,
                     const float* __restrict__ wv, const float* __restrict__ bv,
                     float* __restrict__ qout, float* __restrict__ kout,
                     float* __restrict__ vout) {
    int cb = blockIdx.x;
    int bm = blockIdx.y * 128;
    if (cb < 16) {
        gemm_body<true, false>(x, wq, bq, qout, DMODEL, DMODEL, bm, cb * 128);
    } else if (cb < 20) {
        gemm_body<true, false>(x, wk, bk, kout, KVDIM, DMODEL, bm, (cb - 16) * 128);
    } else {
        gemm_body<true, true>(x, wv, bv, vout, KVDIM, DMODEL, bm, (cb - 20) * 128);
    }
}

// output projection
__global__ __launch_bounds__(256, 2)
void gemm_o_kernel(const float* __restrict__ A, const float* __restrict__ wo,
                   const float* __restrict__ bo, float* __restrict__ C) {
    gemm_body<false, false>(A, wo, bo, C, DMODEL, DMODEL, blockIdx.y * 128, blockIdx.x * 128);
}

// ---------------- LayerNorm + RoPE (in place) ----------------
template <int WIDTH, bool DO_SCALE>
__global__ __launch_bounds__(256)
void ln_rope_kernel(float* __restrict__ x, const float* __restrict__ gamma,
                    const float* __restrict__ beta) {
    constexpr int NT  = 256;
    constexpr int PER = WIDTH / NT;
    __shared__ float sh[WIDTH];
    __shared__ float wred[16];
    __shared__ float s_mu, s_rstd;

    int row = blockIdx.x;
    int t = row & (SEQ - 1);
    float* xr = x + (size_t)row * WIDTH;

    float v[PER];
    float sum = 0.f, sq = 0.f;
#pragma unroll
    for (int i = 0; i < PER; i++) {
        v[i] = xr[threadIdx.x + i * NT];
        sum += v[i];
        sq  += v[i] * v[i];
    }
#pragma unroll
    for (int o = 16; o; o >>= 1) {
        sum += __shfl_xor_sync(0xffffffffu, sum, o);
        sq  += __shfl_xor_sync(0xffffffffu, sq, o);
    }
    int wid = threadIdx.x >> 5, lane = threadIdx.x & 31;
    if (lane == 0) { wred[wid] = sum; wred[8 + wid] = sq; }
    __syncthreads();
    if (threadIdx.x == 0) {
        float s = 0.f, s2 = 0.f;
#pragma unroll
        for (int i = 0; i < 8; i++) { s += wred[i]; s2 += wred[8 + i]; }
        float mu  = s / (float)WIDTH;
        float var = s2 / (float)WIDTH - mu * mu;
        s_mu = mu;
        s_rstd = rsqrtf(var + LN_EPS);
    }
    __syncthreads();
    float mu = s_mu, rstd = s_rstd;
#pragma unroll
    for (int i = 0; i < PER; i++) {
        int e = threadIdx.x + i * NT;
        sh[e] = (v[i] - mu) * rstd * gamma[e] + beta[e];
    }
    __syncthreads();
#pragma unroll
    for (int i = 0; i < PER; i++) {
        int e = threadIdx.x + i * NT;
        int d = e & 127;
        int i64 = d & 63;
        float cc = g_cos[t * 64 + i64];
        float ss = g_sin[t * 64 + i64];
        float val = sh[e];
        float other = (d < 64) ? -sh[e + 64] : sh[e - 64];
        float res = val * cc + other * ss;
        if (DO_SCALE) res *= SCALE;
        xr[e] = __uint_as_float(f2tf(res));
    }
}

// ---------------- MMA flash attention (causal GQA, fixed-offset softmax) ----
// Triangle-balanced grid (NQT/2, BATCH*NHEADS); 33 K-tile iterations per block.
// K fragment loads via ldmatrix; V scalar; Q a-fragments hoisted per pass.
#define ATTN_SMEM_F (64*132 + 2*32*132 + 2*32*132 + 4*16*36)

__global__ __launch_bounds__(128, 2)
void attn_mma_kernel(const float* __restrict__ q, const float* __restrict__ k,
                     const float* __restrict__ v, float* __restrict__ o) {
    extern __shared__ float sm[];
    float* Qs = sm;
    float* Ks = Qs + 64 * 132;
    float* Vs = Ks + 2 * 32 * 132;
    float* Ps = Vs + 2 * 32 * 132;

    const int tid = threadIdx.x;
    const int w = tid >> 5, lane = tid & 31;
    const int r = lane >> 2, c = lane & 3;
    const int bh = blockIdx.y;
    const int b = bh >> 4, h = bh & 15, kvh = h >> 2;

    const float* kbase = k + ((size_t)b * SEQ) * KVDIM + kvh * HDIM;
    const float* vbase = v + ((size_t)b * SEQ) * KVDIM + kvh * HDIM;
    float* Pw = Ps + w * 16 * 36;

    unsigned Ks_base = (unsigned)__cvta_generic_to_shared(Ks);
    const unsigned koff = ((lane & 7) * 132 + ((lane & 8) >> 1)) * 4;

#pragma unroll 1
    for (int pass = 0; pass < 2; pass++) {
        const int qt = pass ? (NQT - 1 - (int)blockIdx.x) : (int)blockIdx.x;
        const int q0 = qt * 64;
        const float* qbase = q + ((size_t)(b * SEQ + q0)) * DMODEL + h * HDIM;

        __syncthreads();

#pragma unroll
        for (int i = 0; i < 16; i++) {
            int idx = tid + i * 128;
            int qr = idx >> 5, d4 = idx & 31;
            *(float4*)&Qs[qr * 132 + d4 * 4] =
                *(const float4*)(qbase + (size_t)qr * DMODEL + d4 * 4);
        }
        __syncthreads();

        unsigned qa[16][4];
#pragma unroll
        for (int kb = 0; kb < 16; kb++) {
            qa[kb][0] = __float_as_uint(Qs[(w * 16 + r) * 132 + kb * 8 + c]);
            qa[kb][1] = __float_as_uint(Qs[(w * 16 + r + 8) * 132 + kb * 8 + c]);
            qa[kb][2] = __float_as_uint(Qs[(w * 16 + r) * 132 + kb * 8 + c + 4]);
            qa[kb][3] = __float_as_uint(Qs[(w * 16 + r + 8) * 132 + kb * 8 + c + 4]);
        }

        auto loadkv = [&](int kt) {
            int buf = kt & 1;
            float* Kd = Ks + buf * 32 * 132;
            float* Vd = Vs + buf * 32 * 132;
            const float* ksrc = kbase + (size_t)(kt * 32) * KVDIM;
            const float* vsrc = vbase + (size_t)(kt * 32) * KVDIM;
#pragma unroll
            for (int i = 0; i < 8; i++) {
                int j = tid + i * 128;
                int row = j >> 5, cc = j & 31;
                unsigned kd = (unsigned)__cvta_generic_to_shared(Kd + row * 132 + cc * 4);
                CP_ASYNC16(kd, ksrc + (size_t)row * KVDIM + cc * 4);
                unsigned vd = (unsigned)__cvta_generic_to_shared(Vd + row * 132 + cc * 4);
                CP_ASYNC16(vd, vsrc + (size_t)row * KVDIM + cc * 4);
            }
        };

        float oacc[16][4];
#pragma unroll
        for (int nb = 0; nb < 16; nb++)
#pragma unroll
            for (int i = 0; i < 4; i++) oacc[nb][i] = 0.f;
        float l0 = 0.f, l1 = 0.f;

        const int row0 = q0 + w * 16 + r;
        const int row1 = row0 + 8;
        const int ntiles = (q0 + 64) >> 5;

        loadkv(0); CP_COMMIT();

        for (int kt = 0; kt < ntiles; kt++) {
            __syncthreads();
            if (kt + 1 < ntiles) loadkv(kt + 1);
            CP_COMMIT();
            CP_WAIT1();
            __syncthreads();

            unsigned kbuf = Ks_base + (kt & 1) * (32 * 132 * 4) + koff;
            const float* Vb = Vs + (kt & 1) * 32 * 132;

            float sacc[4][4];
#pragma unroll
            for (int nb = 0; nb < 4; nb++)
#pragma unroll
                for (int i = 0; i < 4; i++) sacc[nb][i] = 0.f;

#pragma unroll
            for (int kb = 0; kb < 16; kb++) {
#pragma unroll
                for (int nb = 0; nb < 4; nb++) {
                    unsigned b0, b1;
                    LDSM_X2(b0, b1, kbuf + (nb * 8 * 132 + kb * 8) * 4);
                    mma_tf32(sacc[nb], qa[kb][0], qa[kb][1], qa[kb][2], qa[kb][3],
                             b0, b1);
                }
            }

            bool mask_tile = (kt * 32 + 31 > q0 + w * 16);
            __syncwarp();
#pragma unroll
            for (int nb = 0; nb < 4; nb++) {
                int col = kt * 32 + nb * 8 + 2 * c;
                float p0 = __expf(sacc[nb][0] - SMAX_OFF);
                float p1 = __expf(sacc[nb][1] - SMAX_OFF);
                float p2 = __expf(sacc[nb][2] - SMAX_OFF);
                float p3 = __expf(sacc[nb][3] - SMAX_OFF);
                if (mask_tile) {
                    if (col     > row0) p0 = 0.f;
                    if (col + 1 > row0) p1 = 0.f;
                    if (col     > row1) p2 = 0.f;
                    if (col + 1 > row1) p3 = 0.f;
                }
                l0 += p0 + p1;
                l1 += p2 + p3;
                *(float2*)&Pw[r * 36 + nb * 8 + 2 * c] =
                    make_float2(__uint_as_float(f2tf(p0)), __uint_as_float(f2tf(p1)));
                *(float2*)&Pw[(r + 8) * 36 + nb * 8 + 2 * c] =
                    make_float2(__uint_as_float(f2tf(p2)), __uint_as_float(f2tf(p3)));
            }
            __syncwarp();

#pragma unroll
            for (int kb = 0; kb < 4; kb++) {
                unsigned a0 = __float_as_uint(Pw[r * 36 + kb * 8 + c]);
                unsigned a1 = __float_as_uint(Pw[(r + 8) * 36 + kb * 8 + c]);
                unsigned a2 = __float_as_uint(Pw[r * 36 + kb * 8 + c + 4]);
                unsigned a3 = __float_as_uint(Pw[(r + 8) * 36 + kb * 8 + c + 4]);
#pragma unroll
                for (int nb = 0; nb < 16; nb++) {
                    unsigned b0 = __float_as_uint(Vb[(kb * 8 + c) * 132 + nb * 8 + r]);
                    unsigned b1 = __float_as_uint(Vb[(kb * 8 + c + 4) * 132 + nb * 8 + r]);
                    mma_tf32(oacc[nb], a0, a1, a2, a3, b0, b1);
                }
            }
        }

        l0 += __shfl_xor_sync(0xffffffffu, l0, 1);
        l0 += __shfl_xor_sync(0xffffffffu, l0, 2);
        l1 += __shfl_xor_sync(0xffffffffu, l1, 1);
        l1 += __shfl_xor_sync(0xffffffffu, l1, 2);
        float inv0 = 1.f / l0, inv1 = 1.f / l1;

        float* ob0 = o + ((size_t)(b * SEQ + row0)) * DMODEL + h * HDIM;
        float* ob1 = ob0 + (size_t)8 * DMODEL;
#pragma unroll
        for (int nb = 0; nb < 16; nb++) {
            *(float2*)(ob0 + nb * 8 + 2 * c) = make_float2(
                __uint_as_float(f2tf(oacc[nb][0] * inv0)),
                __uint_as_float(f2tf(oacc[nb][1] * inv0)));
            *(float2*)(ob1 + nb * 8 + 2 * c) = make_float2(
                __uint_as_float(f2tf(oacc[nb][2] * inv1)),
                __uint_as_float(f2tf(oacc[nb][3] * inv1)));
        }
    }
}

// ---------------- host launch ----------------
extern "C" void kernel_launch(void* const* d_in, const int* in_sizes, int n_in,
                              void* d_out, int out_size) {
    const float* x       = (const float*)d_in[0];
    const float* wq      = (const float*)d_in[1];
    const float* bq      = (const float*)d_in[2];
    const float* wk      = (const float*)d_in[3];
    const float* bk      = (const float*)d_in[4];
    const float* wv      = (const float*)d_in[5];
    const float* bv      = (const float*)d_in[6];
    const float* wo      = (const float*)d_in[7];
    const float* bo      = (const float*)d_in[8];
    const float* q_gamma = (const float*)d_in[9];
    const float* q_beta  = (const float*)d_in[10];
    const float* k_gamma = (const float*)d_in[11];
    const float* k_beta  = (const float*)d_in[12];
    float* out = (float*)d_out;

    float *qb, *kb, *vb, *ab, *xr, *wqr, *wkr, *wvr, *wor;
    cudaGetSymbolAddress((void**)&qb,  g_q);
    cudaGetSymbolAddress((void**)&kb,  g_k);
    cudaGetSymbolAddress((void**)&vb,  g_v);
    cudaGetSymbolAddress((void**)&ab,  g_att);
    cudaGetSymbolAddress((void**)&xr,  g_xr);
    cudaGetSymbolAddress((void**)&wqr, g_wqr);
    cudaGetSymbolAddress((void**)&wkr, g_wkr);
    cudaGetSymbolAddress((void**)&wvr, g_wvr);
    cudaGetSymbolAddress((void**)&wor, g_wor);

    const int attn_smem = ATTN_SMEM_F * sizeof(float);
    cudaFuncSetAttribute(attn_mma_kernel,
                         cudaFuncAttributeMaxDynamicSharedMemorySize, attn_smem);

    rope_table_kernel<<<(SEQ * 64 + 255) / 256, 256>>>();

    const int NX = NTOK * DMODEL / 4;
    tf32_round_all_kernel<<<dim3((NX + 255) / 256, 5), 256>>>(
        (const float4*)x,  (float4*)xr,
        (const float4*)wq, (float4*)wqr,
        (const float4*)wk, (float4*)wkr,
        (const float4*)wv, (float4*)wvr,
        (const float4*)wo, (float4*)wor);

    gemm_qkv_kernel<<<dim3(24, NTOK / 128), 256>>>(
        xr, wqr, bq, wkr, bk, wvr, bv, qb, kb, vb);

    ln_rope_kernel<DMODEL, true ><<<NTOK, 256>>>(qb, q_gamma, q_beta);
    ln_rope_kernel<KVDIM,  false><<<NTOK, 256>>>(kb, k_gamma, k_beta);

    attn_mma_kernel<<<dim3(NQT / 2, BATCH * NHEADS), 128, attn_smem>>>(qb, kb, vb, ab);

    gemm_o_kernel<<<dim3(DMODEL / 128, NTOK / 128), 256>>>(ab, wor, bo, out);
}